// round 4
// baseline (speedup 1.0000x reference)
#include <cuda_runtime.h>
#include <cstdint>

#define B 8
#define N 100000
#define V 40
#define NBINS 64000                 // V^3
#define NTILES 63                   // ceil(64000/1024)
#define PB_F4 1296000               // float4s per batch in nbr table (V^3*81/4)

// Output layout (float32 elements)
#define O_IDX  0
#define O_HASH 800000
#define O_NBR  1600000
#define O_MASK 43072000

#define NCTA 592                    // 148 SMs * 4 CTAs — one wave, co-resident
#define NTHR 256
#define GSIZE (NCTA * NTHR)         // 151552 threads

// ---- scratch (device globals; zero-initialized at module load) ----
__device__ int g_voxel[B * N];
__device__ int g_hist[B * NBINS];    // counts -> offsets; re-zeroed by finalize
__device__ int g_cursor[B * NBINS];
__device__ int g_sorted[B * N];
__device__ int g_tsum[B * NTILES];
__device__ unsigned g_bar_count;     // grid barrier state
__device__ unsigned g_bar_gen;       // monotone generation (persists across replays)

// ---------------------------------------------------------------------------
// Grid-wide barrier (sense via monotone generation). All NCTA CTAs resident.
__device__ __forceinline__ void grid_barrier(unsigned target) {
    __syncthreads();
    if (threadIdx.x == 0) {
        __threadfence();
        unsigned old = atomicAdd(&g_bar_count, 1u);
        if (old == NCTA - 1) {
            g_bar_count = 0;
            __threadfence();
            atomicAdd(&g_bar_gen, 1u);
        } else {
            volatile unsigned* gen = &g_bar_gen;
            while ((int)(*gen - target) < 0) { __nanosleep(40); }
        }
        __threadfence();
    }
    __syncthreads();
}

// ---------------------------------------------------------------------------
// Neighbour table: one q = one float4 of the batch-invariant layout, streamed
// to all 8 batch copies with evict-first stores.
__device__ __forceinline__ void nbr_q(float* __restrict__ out, int q) {
    int e0  = q * 4;
    int vox = e0 / 81;
    int j0  = e0 - vox * 81;
    int x = vox / (V * V);
    int r = vox - x * (V * V);
    int y = r / V;
    int z = r - y * V;
    int zn = z + 1, yn = y, xn = x;
    if (zn == V) { zn = 0; yn = y + 1; if (yn == V) { yn = 0; xn = x + 1; } }
    float c0[3] = { (float)x,  (float)y,  (float)z  };
    float c1[3] = { (float)xn, (float)yn, (float)zn };

    float4 v;
    float* vp = &v.x;
    #pragma unroll
    for (int k = 0; k < 4; k++) {
        int jk = j0 + k;
        bool w = jk >= 81;
        int jj = w ? jk - 81 : jk;
        int m = jj / 3;
        int c = jj - m * 3;
        int d;
        if (c == 0)      d = m / 9 - 1;
        else if (c == 1) d = (m / 3) % 3 - 1;
        else             d = m % 3 - 1;
        vp[k] = (w ? c1[c] : c0[c]) + (float)d;
    }
    float4* pout = (float4*)(out + O_NBR);
    #pragma unroll
    for (int b = 0; b < B; b++) __stcs(&pout[q + b * PB_F4], v);
}

__device__ __forceinline__ void nbr_range(float* __restrict__ out,
                                          int lo, int hi, int t0, int stride) {
    for (int q = lo + t0; q < hi; q += stride) nbr_q(out, q);
}

// ---------------------------------------------------------------------------
__global__ void __launch_bounds__(NTHR, 6) voxel_mega_kernel(
    const float* __restrict__ pts, float* __restrict__ out) {
    int c   = blockIdx.x;
    int tid = threadIdx.x;
    int gt  = c * NTHR + tid;
    __shared__ int ws[8];

    unsigned gen0 = 0;
    if (tid == 0) gen0 = *(volatile unsigned*)&g_bar_gen;

    // ---- P0: bin (4 points / thread via float4 loads) + nbr [0, 320k) ----
    {
        const float4* p4 = (const float4*)pts;
        for (int g = gt; g < (B * N) / 4; g += GSIZE) {
            float4 f0 = __ldg(&p4[3 * g]);
            float4 f1 = __ldg(&p4[3 * g + 1]);
            float4 f2 = __ldg(&p4[3 * g + 2]);
            int b = g / (N / 4);
            float px[4] = { f0.x, f0.w, f1.z, f2.y };
            float py[4] = { f0.y, f1.x, f1.w, f2.z };
            float pz[4] = { f0.z, f1.y, f2.x, f2.w };
            #pragma unroll
            for (int k = 0; k < 4; k++) {
                int cx = (int)(px[k] * (float)(V - 1));
                int cy = (int)(py[k] * (float)(V - 1));
                int cz = (int)(pz[k] * (float)(V - 1));
                int bin = cx * (V * V) + cy * V + cz;
                g_voxel[4 * g + k] = bin;
                atomicAdd(&g_hist[b * NBINS + bin], 1);
            }
        }
        nbr_range(out, 0, 320000, gt, GSIZE);
    }
    grid_barrier(gen0 + 1);

    // ---- P1a: tile sums (504 CTAs) | nbr [320k, 400k) on the rest ----
    if (c < B * NTILES) {
        int b = c / NTILES;
        int t = c - b * NTILES;
        int tb = t * 1024 + tid * 4;
        int s = 0;
        if (tb < NBINS) {
            int4 v = *(const int4*)(g_hist + b * NBINS + tb);
            s = v.x + v.y + v.z + v.w;
        }
        #pragma unroll
        for (int o = 16; o > 0; o >>= 1) s += __shfl_down_sync(0xFFFFFFFFu, s, o);
        int lane = tid & 31, warp = tid >> 5;
        if (lane == 0) ws[warp] = s;
        __syncthreads();
        if (tid == 0) {
            int tot = 0;
            #pragma unroll
            for (int w = 0; w < 8; w++) tot += ws[w];
            g_tsum[c] = tot;
        }
    } else {
        nbr_range(out, 320000, 400000, (c - B * NTILES) * NTHR + tid,
                  (NCTA - B * NTILES) * NTHR);
    }
    grid_barrier(gen0 + 2);

    // ---- P1b: scan 63 tile sums per batch (8 CTAs, 1 warp) | nbr [400k,520k) ----
    if (c < B) {
        if (tid < 32) {
            int lane = tid;
            int* ts = g_tsum + c * NTILES;
            int v0 = ts[lane];
            int v1 = (lane < NTILES - 32) ? ts[32 + lane] : 0;
            int s0 = v0, s1 = v1;
            #pragma unroll
            for (int o = 1; o < 32; o <<= 1) {
                int t0 = __shfl_up_sync(0xFFFFFFFFu, s0, o);
                int t1 = __shfl_up_sync(0xFFFFFFFFu, s1, o);
                if (lane >= o) { s0 += t0; s1 += t1; }
            }
            int tot0 = __shfl_sync(0xFFFFFFFFu, s0, 31);
            ts[lane] = s0 - v0;
            if (lane < NTILES - 32) ts[32 + lane] = tot0 + s1 - v1;
        }
    } else {
        nbr_range(out, 400000, 520000, (c - B) * NTHR + tid, (NCTA - B) * NTHR);
    }
    grid_barrier(gen0 + 3);

    // ---- P1c: rescan tiles -> offsets + cursors (504 CTAs) | nbr [520k,600k) ----
    if (c < B * NTILES) {
        int b = c / NTILES;
        int t = c - b * NTILES;
        int tb = t * 1024 + tid * 4;
        int4 v = make_int4(0, 0, 0, 0);
        if (tb < NBINS) v = *(const int4*)(g_hist + b * NBINS + tb);
        int tsum = v.x + v.y + v.z + v.w;
        int lane = tid & 31, warp = tid >> 5;
        int x = tsum;
        #pragma unroll
        for (int o = 1; o < 32; o <<= 1) {
            int tt = __shfl_up_sync(0xFFFFFFFFu, x, o);
            if (lane >= o) x += tt;
        }
        if (lane == 31) ws[warp] = x;
        __syncthreads();
        int woff = 0;
        #pragma unroll
        for (int w = 0; w < 8; w++) woff += (w < warp) ? ws[w] : 0;
        int base = g_tsum[c] + woff + x - tsum;
        if (tb < NBINS) {
            int4 o4;
            o4.x = base;
            o4.y = base + v.x;
            o4.z = base + v.x + v.y;
            o4.w = base + v.x + v.y + v.z;
            *(int4*)(g_hist + b * NBINS + tb) = o4;
            *(int4*)(g_cursor + b * NBINS + tb) = o4;
        }
    } else {
        nbr_range(out, 520000, 600000, (c - B * NTILES) * NTHR + tid,
                  (NCTA - B * NTILES) * NTHR);
    }
    grid_barrier(gen0 + 4);

    // ---- P2: scatter + nbr [600k, 960k) ----
    {
        for (int i = gt; i < B * N; i += GSIZE) {
            int b = i / N;
            int n = i - b * N;
            int bin = g_voxel[i];
            int pos = atomicAdd(&g_cursor[b * NBINS + bin], 1);
            g_sorted[b * N + pos] = n;
        }
        nbr_range(out, 600000, 960000, gt, GSIZE);
    }
    grid_barrier(gen0 + 5);

    // ---- P3: finalize (stable fixup + idx/hash/mask, re-zero hist) + nbr tail ----
    {
        for (int t = gt; t < B * NBINS; t += GSIZE) {
            int b = t / NBINS;
            int bin = t - b * NBINS;
            int s = g_hist[b * NBINS + bin];
            int e = g_cursor[b * NBINS + bin];
            g_hist[b * NBINS + bin] = 0;
            int* seg = g_sorted + b * N;
            for (int a = s + 1; a < e; a++) {
                int key = seg[a];
                int j = a - 1;
                while (j >= s && seg[j] > key) { seg[j + 1] = seg[j]; j--; }
                seg[j + 1] = key;
            }
            int cx = bin / (V * V);
            int cy = (bin / V) % V;
            int cz = bin % V;
            float h = (float)(cx * 10000 + cy * 100 + cz);
            for (int j = s; j < e; j++) {
                out[O_IDX  + b * N + j] = (float)seg[j];
                out[O_HASH + b * N + j] = h;
            }
            out[O_MASK + b * NBINS + bin] = (e > s && e < N) ? 1.0f : 0.0f;
        }
        nbr_range(out, 960000, PB_F4, gt, GSIZE);
    }
}

// ---------------------------------------------------------------------------
extern "C" void kernel_launch(void* const* d_in, const int* in_sizes, int n_in,
                              void* d_out, int out_size) {
    const float* pts = (const float*)d_in[0];
    float* out = (float*)d_out;
    voxel_mega_kernel<<<NCTA, NTHR>>>(pts, out);
}